// round 8
// baseline (speedup 1.0000x reference)
#include <cuda_runtime.h>
#include <cuda_bf16.h>
#include <math.h>

#define C    24
#define HC   96
#define FT   48
#define NPOS (FT*FT)
#define P    16           // positions per block (144 blocks = 1 wave)
#define NBLK (NPOS / P)   // 144
#define XNORM_A 0.007843137718737125f
#define DELTA 1.8f
#define OUT_SCALE 0.02083333395421505f

// Dense hm_hp logits, channel-major [ch][pos]
__device__ float g_hmhp[17 * NPOS];
// Per-block center argmax keys: (score_bits<<32) | (0xFFFFFFFF - pos)
__device__ unsigned long long g_part[NBLK];
// Per-block hps head evaluated at the block's local-best position [blk][34]
__device__ float g_kreg[NBLK * 34];

__device__ __forceinline__ float fast_sig(float v) {
    return __fdividef(1.0f, 1.0f + __expf(-v));
}

// ---------------------------------------------------------------------------
// Kernel 1: dense hm_hp(17)+hm(1) heads, per-block center key, and the hps
// head evaluated at the block's local-best center candidate.
// 144 blocks x 256 threads.
// ---------------------------------------------------------------------------
__global__ __launch_bounds__(256) void heads_kernel(
    const float* __restrict__ x,
    const float* __restrict__ w_dw0, const float* __restrict__ b_dw0,  // hm_hp
    const float* __restrict__ w1_0,  const float* __restrict__ b1_0,
    const float* __restrict__ w2_0,  const float* __restrict__ b2_0,
    const float* __restrict__ w_dw1, const float* __restrict__ b_dw1,  // hm
    const float* __restrict__ w1_1,  const float* __restrict__ b1_1,
    const float* __restrict__ w2_1,  const float* __restrict__ b2_1,
    const float* __restrict__ hps_dw_w, const float* __restrict__ hps_dw_b,
    const float* __restrict__ hps_w1,   const float* __restrict__ hps_b1,
    const float* __restrict__ hps_w2,   const float* __restrict__ hps_b2)
{
    __shared__ float xs[C][3][P + 2];     // normalized input tile (zero padded)
    __shared__ float ys[2][P][28];        // depthwise outputs, padded stride
    __shared__ float zs[2][P][100];       // pw1+relu outputs, padded stride
    __shared__ unsigned long long skey[P];
    __shared__ int   s_ploc;
    __shared__ float s_y[C];
    __shared__ float s_z[HC];

    const int tid   = threadIdx.x;
    const int lane  = tid & 31;
    const int wid   = tid >> 5;
    const int pbase = blockIdx.x * P;     // 48 % 16 == 0 -> all same row
    const int row   = pbase / FT;
    const int col0  = pbase % FT;

    // ---- stage X: normalized 3x(P+2) neighborhood, all 24 channels
    for (int idx = tid; idx < C * 3 * (P + 2); idx += 256) {
        int c  = idx / (3 * (P + 2));
        int r  = (idx / (P + 2)) % 3;
        int cc = idx % (P + 2);
        int gi = row + r - 1;
        int gj = col0 + cc - 1;
        float v = 0.f;
        if (gi >= 0 && gi < FT && gj >= 0 && gj < FT)
            v = x[(c * FT + gi) * FT + gj] * XNORM_A - 1.0f;
        xs[c][r][cc] = v;
    }
    __syncthreads();

    // ---- stage Y: depthwise 3x3, 2 heads: 768 values
    for (int idx = tid; idx < 2 * C * P; idx += 256) {
        int h   = idx / (C * P);
        int rem = idx % (C * P);
        int c   = rem / P;
        int p   = rem % P;
        const float* wd = h ? w_dw1 : w_dw0;
        const float* bd = h ? b_dw1 : b_dw0;
        float acc = bd[c];
        #pragma unroll
        for (int r = 0; r < 3; r++)
            #pragma unroll
            for (int s = 0; s < 3; s++)
                acc += wd[c * 9 + r * 3 + s] * xs[c][r][p + s];
        ys[h][p][c] = acc;
    }
    __syncthreads();

    // ---- stage Z: pw1 (24->96) + relu, 2 heads: 192 rows
    if (tid < 2 * HC) {
        int h  = tid / HC;
        int oc = tid % HC;
        const float* w1 = h ? w1_1 : w1_0;
        const float* b1 = h ? b1_1 : b1_0;
        float acc[P];
        float b = b1[oc];
        #pragma unroll
        for (int p = 0; p < P; p++) acc[p] = b;
        #pragma unroll
        for (int k = 0; k < C; k++) {
            float wv = __ldg(&w1[oc * C + k]);
            #pragma unroll
            for (int p = 0; p < P; p++) acc[p] += wv * ys[h][p][k];
        }
        #pragma unroll
        for (int p = 0; p < P; p++) zs[h][p][oc] = fmaxf(acc[p], 0.f);
    }
    __syncthreads();

    // ---- stage O: pw2. hm_hp 17ch + hm 1ch = 288 items
    for (int idx = tid; idx < 18 * P; idx += 256) {
        int combo = idx / P;
        int p     = idx % P;
        int pos   = pbase + p;
        if (combo < 17) {
            int oc = combo;
            float acc = b2_0[oc];
            #pragma unroll 8
            for (int k = 0; k < HC; k++)
                acc += __ldg(&w2_0[oc * HC + k]) * zs[0][p][k];
            g_hmhp[oc * NPOS + pos] = acc;
        } else {
            float acc = b2_1[0];
            #pragma unroll 8
            for (int k = 0; k < HC; k++)
                acc += __ldg(&w2_1[k]) * zs[1][p][k];
            float sig = fast_sig(acc);
            float gy = (float)row - (FT * 0.5f);
            float gx = (float)(col0 + p) - (FT * 0.5f);
            float s = __fdividef(sig, sqrtf(gy * gy + gx * gx) + DELTA);
            skey[p] = ((unsigned long long)__float_as_uint(s) << 32)
                    | (unsigned long long)(0xFFFFFFFFu - (unsigned)pos);
        }
    }
    __syncthreads();

    // ---- local best center candidate + publish key
    if (tid == 0) {
        unsigned long long best = skey[0];
        #pragma unroll
        for (int p = 1; p < P; p++) if (skey[p] > best) best = skey[p];
        g_part[blockIdx.x] = best;
        s_ploc = (int)(0xFFFFFFFFu - (unsigned)(best & 0xFFFFFFFFu)) - pbase;
    }
    __syncthreads();

    // ---- hps head at the local-best position (from the smem x tile)
    const int pl = s_ploc;
    if (tid < C) {
        float acc = hps_dw_b[tid];
        #pragma unroll
        for (int r = 0; r < 3; r++)
            #pragma unroll
            for (int s = 0; s < 3; s++)
                acc += __ldg(&hps_dw_w[tid * 9 + r * 3 + s]) * xs[tid][r][pl + s];
        s_y[tid] = acc;
    }
    __syncthreads();
    if (tid < HC) {
        float a = hps_b1[tid];
        #pragma unroll
        for (int kk = 0; kk < C; kk++) a += __ldg(&hps_w1[tid * C + kk]) * s_y[kk];
        s_z[tid] = fmaxf(a, 0.f);
    }
    __syncthreads();
    // 34 output channels, warp-parallel dots (warp w handles ch = w, w+8, ...)
    for (int ch = wid; ch < 34; ch += 8) {
        float a = __ldg(&hps_w2[ch * HC + lane])      * s_z[lane]
                + __ldg(&hps_w2[ch * HC + lane + 32]) * s_z[lane + 32]
                + __ldg(&hps_w2[ch * HC + lane + 64]) * s_z[lane + 64];
        #pragma unroll
        for (int off = 16; off; off >>= 1)
            a += __shfl_down_sync(0xffffffffu, a, off);
        if (lane == 0)
            g_kreg[blockIdx.x * 34 + ch] = a + hps_b2[ch];
    }
}

// ---------------------------------------------------------------------------
// Kernel 2: decode, 17 blocks x 256 threads.
// ---------------------------------------------------------------------------
__global__ __launch_bounds__(256) void decode_kernel(
    const float* __restrict__ x,
    const float* __restrict__ off_dw_w, const float* __restrict__ off_dw_b,
    const float* __restrict__ off_w1,   const float* __restrict__ off_b1,
    const float* __restrict__ off_w2,   const float* __restrict__ off_b2,
    float* __restrict__ out)
{
    __shared__ float s_ow1[HC * C];   // 9216 B
    __shared__ float s_odw[C * 9];
    __shared__ float s_odb[C];
    __shared__ float s_ob1[HC];
    __shared__ float s_v[8];
    __shared__ int   s_i[8];
    __shared__ int   s_ct, s_top;
    __shared__ float s_y[C];
    __shared__ float s_z[HC];
    __shared__ float s_kc[2];

    const int k    = blockIdx.x;
    const int tid  = threadIdx.x;
    const int lane = tid & 31;
    const int wid  = tid >> 5;

    // ---- A: warp 0 reduces the 144 center keys; warps 1..7 prefetch
    //       hp_offset weights into smem concurrently.
    if (wid == 0) {
        unsigned long long key = 0ULL;
        for (int i = lane; i < NBLK; i += 32) {
            unsigned long long v = g_part[i];
            if (v > key) key = v;
        }
        #pragma unroll
        for (int off = 16; off; off >>= 1) {
            unsigned long long o = __shfl_down_sync(0xffffffffu, key, off);
            if (o > key) key = o;
        }
        if (lane == 0)
            s_ct = (int)(0xFFFFFFFFu - (unsigned)(key & 0xFFFFFFFFu));
    } else {
        int t = tid - 32;                 // 0..223
        for (int i = t; i < HC * C; i += 224) s_ow1[i] = __ldg(&off_w1[i]);
        if (t < HC) s_ob1[t] = __ldg(&off_b1[t]);                      // 0..95
        int u = t - HC;                                                 // 96..223 -> 0..127
        if (u >= 0 && u < C * 9 + C) {
            if (u < C * 9) s_odw[u] = __ldg(&off_dw_w[u]);              // needs 216... u max 127
        }
        // remaining s_odw entries + s_odb: second pass by all 224 threads
        if (t < C) s_odb[t] = __ldg(&off_dw_b[t]);
        for (int i = t + 128; i < C * 9; i += 224)                      // covers 128..215
            s_odw[i] = __ldg(&off_dw_w[i]);
    }
    __syncthreads();

    const int ct  = s_ct;
    const int cty = ct / FT, ctx = ct % FT;
    const int bsrc = ct / P;              // block that owns ct

    // ---- B': gather kpt_coor (2 floats)
    if (tid < 2)
        s_kc[tid] = g_kreg[bsrc * 34 + 2 * k + tid] + (tid ? (float)ctx : (float)cty);
    __syncthreads();

    // ---- C: distance-weighted argmax over this keypoint's heatmap
    const float ky = s_kc[0];
    const float kx = s_kc[1];
    const float* hmap = g_hmhp + k * NPOS;
    {
        float bv = -1e30f; int bi = 0x7fffffff;
        #pragma unroll
        for (int i = 0; i < NPOS / 256; i++) {
            int p = tid + i * 256;
            float sig = fast_sig(__ldg(&hmap[p]));
            int py = p / FT;
            float dy = (float)py - ky;
            float dx = (float)(p - py * FT) - kx;
            float s = __fdividef(sig, sqrtf(dy * dy + dx * dx) + DELTA);
            if (s > bv || (s == bv && p < bi)) { bv = s; bi = p; }
        }
        #pragma unroll
        for (int off = 16; off; off >>= 1) {
            float ov = __shfl_down_sync(0xffffffffu, bv, off);
            int   oi = __shfl_down_sync(0xffffffffu, bi, off);
            if (ov > bv || (ov == bv && oi < bi)) { bv = ov; bi = oi; }
        }
        if (lane == 0) { s_v[wid] = bv; s_i[wid] = bi; }
        __syncthreads();
        if (tid == 0) {
            float xv = s_v[0]; int xi = s_i[0];
            #pragma unroll
            for (int w = 1; w < 8; w++) {
                if (s_v[w] > xv || (s_v[w] == xv && s_i[w] < xi)) {
                    xv = s_v[w]; xi = s_i[w];
                }
            }
            s_top = xi;
        }
        __syncthreads();
    }
    const int top = s_top;
    const int ty  = top / FT, tx = top % FT;

    // ---- D: hp_offset head at the winner, weights from smem
    if (tid < C) {
        float acc = s_odb[tid];
        #pragma unroll
        for (int r = 0; r < 3; r++) {
            int gi = ty + r - 1;
            if (gi < 0 || gi >= FT) continue;
            #pragma unroll
            for (int s = 0; s < 3; s++) {
                int gj = tx + s - 1;
                if (gj < 0 || gj >= FT) continue;
                float xv = __ldg(&x[(tid * FT + gi) * FT + gj]) * XNORM_A - 1.0f;
                acc += s_odw[tid * 9 + r * 3 + s] * xv;
            }
        }
        s_y[tid] = acc;
    }
    __syncthreads();
    if (tid < HC) {
        float a = s_ob1[tid];
        #pragma unroll
        for (int kk = 0; kk < C; kk++) a += s_ow1[tid * C + kk] * s_y[kk];
        s_z[tid] = fmaxf(a, 0.f);
    }
    __syncthreads();
    if (wid < 2) {
        int oc = 2 * k + wid;
        float a = __ldg(&off_w2[oc * HC + lane])      * s_z[lane]
                + __ldg(&off_w2[oc * HC + lane + 32]) * s_z[lane + 32]
                + __ldg(&off_w2[oc * HC + lane + 64]) * s_z[lane + 64];
        #pragma unroll
        for (int off = 16; off; off >>= 1)
            a += __shfl_down_sync(0xffffffffu, a, off);
        if (lane == 0) {
            float base = wid ? (float)tx : (float)ty;
            out[k * 3 + wid] = (a + __ldg(&off_b2[oc]) + base) * OUT_SCALE;
        }
    }
    if (tid == 64)   // precise sigmoid for reported confidence
        out[k * 3 + 2] = 1.0f / (1.0f + expf(-hmap[top]));
}

// ---------------------------------------------------------------------------
extern "C" void kernel_launch(void* const* d_in, const int* in_sizes, int n_in,
                              void* d_out, int out_size)
{
    const float* x = (const float*)d_in[0];
    heads_kernel<<<NBLK, 256>>>(
        x,
        (const float*)d_in[1],  (const float*)d_in[2],
        (const float*)d_in[3],  (const float*)d_in[4],
        (const float*)d_in[5],  (const float*)d_in[6],
        (const float*)d_in[7],  (const float*)d_in[8],
        (const float*)d_in[9],  (const float*)d_in[10],
        (const float*)d_in[11], (const float*)d_in[12],
        (const float*)d_in[13], (const float*)d_in[14],
        (const float*)d_in[15], (const float*)d_in[16],
        (const float*)d_in[17], (const float*)d_in[18]);

    decode_kernel<<<17, 256>>>(
        x,
        (const float*)d_in[19], (const float*)d_in[20],
        (const float*)d_in[21], (const float*)d_in[22],
        (const float*)d_in[23], (const float*)d_in[24],
        (float*)d_out);
}

// round 9
// speedup vs baseline: 1.0808x; 1.0808x over previous
#include <cuda_runtime.h>
#include <cuda_bf16.h>
#include <math.h>

#define C    24
#define HC   96
#define FT   48
#define NPOS (FT*FT)
#define P    16           // positions per block (144 blocks = 1 wave)
#define NBLK (NPOS / P)   // 144
#define XNORM_A 0.007843137718737125f
#define DELTA 1.8f
#define OUT_SCALE 0.02083333395421505f

// Dense hm_hp SIGMOIDS, channel-major [ch][pos]
__device__ float g_hmhp[17 * NPOS];
// Per-block center argmax keys: (score_bits<<32) | (0xFFFFFFFF - pos)
__device__ unsigned long long g_part[NBLK];

__device__ __forceinline__ float fast_sig(float v) {
    return __fdividef(1.0f, 1.0f + __expf(-v));
}

// depthwise-3x3 at a single position/channel, with input normalization + zero pad
__device__ __forceinline__ float dw_at(const float* __restrict__ x,
                                       const float* __restrict__ wd,
                                       const float* __restrict__ bd,
                                       int c, int i, int j)
{
    float acc = bd[c];
    #pragma unroll
    for (int r = 0; r < 3; r++) {
        int gi = i + r - 1;
        if (gi < 0 || gi >= FT) continue;
        #pragma unroll
        for (int s = 0; s < 3; s++) {
            int gj = j + s - 1;
            if (gj < 0 || gj >= FT) continue;
            float xv = x[(c * FT + gi) * FT + gj] * XNORM_A - 1.0f;
            acc += wd[c * 9 + r * 3 + s] * xv;
        }
    }
    return acc;
}

// ---------------------------------------------------------------------------
// Kernel 1: dense hm_hp (17ch, stored as sigmoid) + hm (1ch) heads +
// per-block center argmax key. 144 blocks x 256 threads.
// ---------------------------------------------------------------------------
__global__ __launch_bounds__(256) void heads_kernel(
    const float* __restrict__ x,
    const float* __restrict__ w_dw0, const float* __restrict__ b_dw0,
    const float* __restrict__ w1_0,  const float* __restrict__ b1_0,
    const float* __restrict__ w2_0,  const float* __restrict__ b2_0,
    const float* __restrict__ w_dw1, const float* __restrict__ b_dw1,
    const float* __restrict__ w1_1,  const float* __restrict__ b1_1,
    const float* __restrict__ w2_1,  const float* __restrict__ b2_1)
{
    __shared__ float xs[C][3][P + 2];     // normalized input tile (zero padded)
    __shared__ float ys[2][P][28];        // depthwise outputs, padded stride
    __shared__ float zs[2][P][100];       // pw1+relu outputs, padded stride
    __shared__ unsigned long long skey[P];

    const int tid   = threadIdx.x;
    const int pbase = blockIdx.x * P;     // 48 % 16 == 0 -> all same row
    const int row   = pbase / FT;
    const int col0  = pbase % FT;

    // ---- stage X
    for (int idx = tid; idx < C * 3 * (P + 2); idx += 256) {
        int c  = idx / (3 * (P + 2));
        int r  = (idx / (P + 2)) % 3;
        int cc = idx % (P + 2);
        int gi = row + r - 1;
        int gj = col0 + cc - 1;
        float v = 0.f;
        if (gi >= 0 && gi < FT && gj >= 0 && gj < FT)
            v = x[(c * FT + gi) * FT + gj] * XNORM_A - 1.0f;
        xs[c][r][cc] = v;
    }
    __syncthreads();

    // ---- stage Y: depthwise 3x3, 2 heads
    for (int idx = tid; idx < 2 * C * P; idx += 256) {
        int h   = idx / (C * P);
        int rem = idx % (C * P);
        int c   = rem / P;
        int p   = rem % P;
        const float* wd = h ? w_dw1 : w_dw0;
        const float* bd = h ? b_dw1 : b_dw0;
        float acc = bd[c];
        #pragma unroll
        for (int r = 0; r < 3; r++)
            #pragma unroll
            for (int s = 0; s < 3; s++)
                acc += wd[c * 9 + r * 3 + s] * xs[c][r][p + s];
        ys[h][p][c] = acc;
    }
    __syncthreads();

    // ---- stage Z: pw1 (24->96) + relu
    if (tid < 2 * HC) {
        int h  = tid / HC;
        int oc = tid % HC;
        const float* w1 = h ? w1_1 : w1_0;
        const float* b1 = h ? b1_1 : b1_0;
        float acc[P];
        float b = b1[oc];
        #pragma unroll
        for (int p = 0; p < P; p++) acc[p] = b;
        #pragma unroll
        for (int k = 0; k < C; k++) {
            float wv = __ldg(&w1[oc * C + k]);
            #pragma unroll
            for (int p = 0; p < P; p++) acc[p] += wv * ys[h][p][k];
        }
        #pragma unroll
        for (int p = 0; p < P; p++) zs[h][p][oc] = fmaxf(acc[p], 0.f);
    }
    __syncthreads();

    // ---- stage O: pw2. hm_hp (17ch, store sigmoid) + hm (1ch, center key)
    for (int idx = tid; idx < 18 * P; idx += 256) {
        int combo = idx / P;
        int p     = idx % P;
        int pos   = pbase + p;
        if (combo < 17) {
            int oc = combo;
            float acc = b2_0[oc];
            #pragma unroll 8
            for (int k = 0; k < HC; k++)
                acc += __ldg(&w2_0[oc * HC + k]) * zs[0][p][k];
            g_hmhp[oc * NPOS + pos] = fast_sig(acc);
        } else {
            float acc = b2_1[0];
            #pragma unroll 8
            for (int k = 0; k < HC; k++)
                acc += __ldg(&w2_1[k]) * zs[1][p][k];
            float sig = fast_sig(acc);
            float gy = (float)row - (FT * 0.5f);
            float gx = (float)(col0 + p) - (FT * 0.5f);
            float s = __fdividef(sig, sqrtf(gy * gy + gx * gx) + DELTA);
            skey[p] = ((unsigned long long)__float_as_uint(s) << 32)
                    | (unsigned long long)(0xFFFFFFFFu - (unsigned)pos);
        }
    }
    __syncthreads();
    if (tid == 0) {
        unsigned long long best = skey[0];
        #pragma unroll
        for (int p = 1; p < P; p++) if (skey[p] > best) best = skey[p];
        g_part[blockIdx.x] = best;
    }
}

// ---------------------------------------------------------------------------
// Kernel 2: decode, 17 blocks x 256 threads.
// ---------------------------------------------------------------------------
__global__ __launch_bounds__(256) void decode_kernel(
    const float* __restrict__ x,
    const float* __restrict__ hps_dw_w, const float* __restrict__ hps_dw_b,
    const float* __restrict__ hps_w1,   const float* __restrict__ hps_b1,
    const float* __restrict__ hps_w2,   const float* __restrict__ hps_b2,
    const float* __restrict__ off_dw_w, const float* __restrict__ off_dw_b,
    const float* __restrict__ off_w1,   const float* __restrict__ off_b1,
    const float* __restrict__ off_w2,   const float* __restrict__ off_b2,
    float* __restrict__ out)
{
    __shared__ unsigned long long s_k[8];
    __shared__ int   s_ct, s_top;
    __shared__ float s_y[C];
    __shared__ float s_z[HC];
    __shared__ float s_kc[2];

    const int k    = blockIdx.x;
    const int tid  = threadIdx.x;
    const int lane = tid & 31;
    const int wid  = tid >> 5;

    // ---- A: reduce 144 per-block center keys (warp 0)
    if (wid == 0) {
        unsigned long long key = 0ULL;
        for (int i = lane; i < NBLK; i += 32) {
            unsigned long long v = g_part[i];
            if (v > key) key = v;
        }
        #pragma unroll
        for (int off = 16; off; off >>= 1) {
            unsigned long long o = __shfl_down_sync(0xffffffffu, key, off);
            if (o > key) key = o;
        }
        if (lane == 0)
            s_ct = (int)(0xFFFFFFFFu - (unsigned)(key & 0xFFFFFFFFu));
    }
    __syncthreads();
    const int ct  = s_ct;
    const int cty = ct / FT, ctx = ct % FT;

    // ---- B: hps head at the center (channels 2k, 2k+1)
    if (tid < C)
        s_y[tid] = dw_at(x, hps_dw_w, hps_dw_b, tid, cty, ctx);
    __syncthreads();
    if (tid < HC) {
        float a = hps_b1[tid];
        #pragma unroll
        for (int kk = 0; kk < C; kk++) a += __ldg(&hps_w1[tid * C + kk]) * s_y[kk];
        s_z[tid] = fmaxf(a, 0.f);
    }
    __syncthreads();
    if (wid < 2) {
        int oc = 2 * k + wid;
        float a = __ldg(&hps_w2[oc * HC + lane])      * s_z[lane]
                + __ldg(&hps_w2[oc * HC + lane + 32]) * s_z[lane + 32]
                + __ldg(&hps_w2[oc * HC + lane + 64]) * s_z[lane + 64];
        #pragma unroll
        for (int off = 16; off; off >>= 1)
            a += __shfl_down_sync(0xffffffffu, a, off);
        if (lane == 0)
            s_kc[wid] = a + hps_b2[oc] + (wid ? (float)ctx : (float)cty);
    }
    __syncthreads();

    // ---- C: distance-weighted argmax, u64-key max (no serial compare chain)
    const float ky = s_kc[0];
    const float kx = s_kc[1];
    const float* hmap = g_hmhp + k * NPOS;   // sigmoids, precomputed
    {
        unsigned long long best = 0ULL;
        #pragma unroll
        for (int i = 0; i < NPOS / 256; i++) {
            int p = tid + i * 256;
            float sig = __ldg(&hmap[p]);
            int py = p / FT;
            float dy = (float)py - ky;
            float dx = (float)(p - py * FT) - kx;
            float s = __fdividef(sig, sqrtf(dy * dy + dx * dx) + DELTA);
            // s > 0 always -> float bit pattern is order-preserving
            unsigned long long key =
                ((unsigned long long)__float_as_uint(s) << 32)
                | (unsigned long long)(0xFFFFFFFFu - (unsigned)p);
            if (key > best) best = key;
        }
        #pragma unroll
        for (int off = 16; off; off >>= 1) {
            unsigned long long o = __shfl_down_sync(0xffffffffu, best, off);
            if (o > best) best = o;
        }
        if (lane == 0) s_k[wid] = best;
        __syncthreads();
        if (tid == 0) {
            unsigned long long b = s_k[0];
            #pragma unroll
            for (int w = 1; w < 8; w++) if (s_k[w] > b) b = s_k[w];
            s_top = (int)(0xFFFFFFFFu - (unsigned)(b & 0xFFFFFFFFu));
        }
        __syncthreads();
    }
    const int top = s_top;
    const int ty  = top / FT, tx = top % FT;

    // ---- D: hp_offset head at the winner (channels 2k, 2k+1) + outputs
    if (tid < C)
        s_y[tid] = dw_at(x, off_dw_w, off_dw_b, tid, ty, tx);
    __syncthreads();
    if (tid < HC) {
        float a = off_b1[tid];
        #pragma unroll
        for (int kk = 0; kk < C; kk++) a += __ldg(&off_w1[tid * C + kk]) * s_y[kk];
        s_z[tid] = fmaxf(a, 0.f);
    }
    __syncthreads();
    if (wid < 2) {
        int oc = 2 * k + wid;
        float a = __ldg(&off_w2[oc * HC + lane])      * s_z[lane]
                + __ldg(&off_w2[oc * HC + lane + 32]) * s_z[lane + 32]
                + __ldg(&off_w2[oc * HC + lane + 64]) * s_z[lane + 64];
        #pragma unroll
        for (int off = 16; off; off >>= 1)
            a += __shfl_down_sync(0xffffffffu, a, off);
        if (lane == 0) {
            float base = wid ? (float)tx : (float)ty;
            out[k * 3 + wid] = (a + off_b2[oc] + base) * OUT_SCALE;
        }
    }
    if (tid == 64)   // confidence = stored sigmoid at the winner
        out[k * 3 + 2] = hmap[top];
}

// ---------------------------------------------------------------------------
extern "C" void kernel_launch(void* const* d_in, const int* in_sizes, int n_in,
                              void* d_out, int out_size)
{
    const float* x = (const float*)d_in[0];
    heads_kernel<<<NBLK, 256>>>(
        x,
        (const float*)d_in[1],  (const float*)d_in[2],
        (const float*)d_in[3],  (const float*)d_in[4],
        (const float*)d_in[5],  (const float*)d_in[6],
        (const float*)d_in[7],  (const float*)d_in[8],
        (const float*)d_in[9],  (const float*)d_in[10],
        (const float*)d_in[11], (const float*)d_in[12]);

    decode_kernel<<<17, 256>>>(
        x,
        (const float*)d_in[13], (const float*)d_in[14],
        (const float*)d_in[15], (const float*)d_in[16],
        (const float*)d_in[17], (const float*)d_in[18],
        (const float*)d_in[19], (const float*)d_in[20],
        (const float*)d_in[21], (const float*)d_in[22],
        (const float*)d_in[23], (const float*)d_in[24],
        (float*)d_out);
}